// round 1
// baseline (speedup 1.0000x reference)
#include <cuda_runtime.h>

#define B_    16
#define CIN   32
#define COUT  32
#define H_    256
#define W_    256
#define EMB2  512
#define XPITCH 72   // 66 cols padded

typedef unsigned long long u64;

__device__ float g_wadapt[B_ * CIN];   // per-sample input-channel scale
__device__ float g_bfinal[B_ * COUT];  // bias[o] * badapt[b,o]

// ---------------------------------------------------------------------------
// f32x2 packed helpers (Blackwell packed fp32 FMA — 2x scalar FFMA rate)
// ---------------------------------------------------------------------------
__device__ __forceinline__ u64 pack2(float lo, float hi) {
    u64 r;
    asm("mov.b64 %0, {%1, %2};" : "=l"(r)
        : "r"(__float_as_uint(lo)), "r"(__float_as_uint(hi)));
    return r;
}
__device__ __forceinline__ void unpack2(u64 v, float& lo, float& hi) {
    unsigned a, b;
    asm("mov.b64 {%0, %1}, %2;" : "=r"(a), "=r"(b) : "l"(v));
    lo = __uint_as_float(a);
    hi = __uint_as_float(b);
}
__device__ __forceinline__ void fma2(u64& d, u64 a, u64 b) {
    asm("fma.rn.f32x2 %0, %1, %2, %0;" : "+l"(d) : "l"(a), "l"(b));
}

// ---------------------------------------------------------------------------
// Kernel A: wadapt[b,c] = concat(cond,lpe)[b] . wa_w[c] + wa_b[c]
//           bfinal[b,c] = bias[c] * (concat(cond,lpe)[b] . ba_w[c] + ba_b[c])
// One warp per dot product (1024 dots total).
// ---------------------------------------------------------------------------
__global__ void adapt_kernel(const float* __restrict__ cond,
                             const float* __restrict__ lpe,
                             const float* __restrict__ wa_w,
                             const float* __restrict__ wa_b,
                             const float* __restrict__ ba_w,
                             const float* __restrict__ ba_b,
                             const float* __restrict__ bias) {
    int gw   = blockIdx.x * (blockDim.x >> 5) + (threadIdx.x >> 5);
    int lane = threadIdx.x & 31;
    if (gw >= 2 * B_ * CIN) return;
    int isB = (gw >= B_ * CIN);
    int idx = isB ? gw - B_ * CIN : gw;
    int b = idx >> 5, c = idx & 31;

    const float4* w4 = (const float4*)((isB ? ba_w : wa_w) + c * EMB2);
    const float4* c4 = (const float4*)(cond + b * 256);
    const float4* l4 = (const float4*)(lpe  + b * 256);

    float s = 0.f;
#pragma unroll
    for (int k = 0; k < 4; k++) {
        int j = lane + 32 * k;               // float4 index 0..127
        float4 iv = (j < 64) ? c4[j] : l4[j - 64];
        float4 wv = w4[j];
        s += iv.x * wv.x + iv.y * wv.y + iv.z * wv.z + iv.w * wv.w;
    }
#pragma unroll
    for (int off = 16; off; off >>= 1) s += __shfl_xor_sync(0xffffffffu, s, off);

    if (lane == 0) {
        if (isB) g_bfinal[idx] = bias[c] * (s + ba_b[c]);
        else     g_wadapt[idx] = s + wa_b[c];
    }
}

// ---------------------------------------------------------------------------
// Kernel B: shared-weight 3x3 SAME conv on wadapt-scaled weights.
// Block: 256 thr = 8 warps. Tile: 64 (w) x 4 (h) pixels, one batch sample,
// all 32 Cout. Warp w owns Cout [4w, 4w+4); lane l owns columns {2l, 2l+1}
// (the two f32x2 lanes) x 4 rows.
// SMEM: ws = broadcast-duplicated (w*wadapt, w*wadapt) u64 [cin][o][kl] 72KB
//       xs = input tile with halo [cin][6][72] 54KB
// ---------------------------------------------------------------------------
#define WS_U64   (CIN * COUT * 9)                 // 9216
#define XS_FLT   (CIN * 6 * XPITCH)
#define SMEM_BYTES (WS_U64 * 8 + XS_FLT * 4)      // 73728 + 55296 = 129024

__global__ void __launch_bounds__(256, 1)
conv_kernel(const float* __restrict__ x,
            const float* __restrict__ weights,
            float* __restrict__ out) {
    extern __shared__ __align__(16) char smem_raw[];
    u64*   ws = (u64*)smem_raw;
    float* xs = (float*)(smem_raw + WS_U64 * 8);
    __shared__ float wad[CIN];

    const int tid = threadIdx.x;
    const int b   = blockIdx.z;
    const int gy0 = blockIdx.y * 4;
    const int gx0 = blockIdx.x * 64;

    if (tid < CIN) wad[tid] = g_wadapt[b * CIN + tid];
    __syncthreads();

    // Fill ws: linear index e == weights layout [i][o][kl]; scale by wadapt[b,i],
    // duplicate into both f32x2 lanes.
#pragma unroll
    for (int k = 0; k < 36; k++) {
        int e = tid + k * 256;                    // 0..9215 exactly
        int i = e / 288;
        float v = weights[e] * wad[i];
        ws[e] = pack2(v, v);
    }

    // Fill xs tile with halo (zero padding at image borders).
    const float* xb = x + (size_t)b * CIN * H_ * W_;
    for (int e = tid; e < CIN * 6 * 66; e += 256) {
        int c = e % 66;
        int t = e / 66;
        int r = t % 6;
        int i = t / 6;
        int gy = gy0 + r - 1;
        int gx = gx0 + c - 1;
        float v = 0.f;
        if (gy >= 0 && gy < H_ && gx >= 0 && gx < W_)
            v = xb[(size_t)i * (H_ * W_) + gy * W_ + gx];
        xs[(i * 6 + r) * XPITCH + c] = v;
    }
    __syncthreads();

    const int warp  = tid >> 5;
    const int lane  = tid & 31;
    const int obase = warp * 4;
    const int cx    = 2 * lane;

    u64 acc[4][4];
#pragma unroll
    for (int r = 0; r < 4; r++)
#pragma unroll
        for (int o = 0; o < 4; o++) acc[r][o] = 0ULL;

    for (int ci = 0; ci < CIN; ci++) {
        // x window: 6 rows x 4 cols -> 3 column-pair variants per row
        u64 xp[6][3];
        const float* xr = xs + (ci * 6) * XPITCH + cx;
#pragma unroll
        for (int r = 0; r < 6; r++) {
            u64 a0 = *(const u64*)(xr + r * XPITCH);       // (x0,x1)
            u64 a2 = *(const u64*)(xr + r * XPITCH + 2);   // (x2,x3)
            float f0, f1, f2, f3;
            unpack2(a0, f0, f1);
            unpack2(a2, f2, f3);
            xp[r][0] = a0;
            xp[r][1] = pack2(f1, f2);
            xp[r][2] = a2;
        }

        const u64* wrow = ws + ci * 288 + obase * 9;
#pragma unroll
        for (int kr = 0; kr < 3; kr++) {
#pragma unroll
            for (int kc = 0; kc < 3; kc++) {
                const int kl = kr * 3 + kc;
                u64 w0 = wrow[kl];
                u64 w1 = wrow[9  + kl];
                u64 w2 = wrow[18 + kl];
                u64 w3 = wrow[27 + kl];
#pragma unroll
                for (int r = 0; r < 4; r++) {
                    u64 xv = xp[r + kr][kc];
                    fma2(acc[r][0], xv, w0);
                    fma2(acc[r][1], xv, w1);
                    fma2(acc[r][2], xv, w2);
                    fma2(acc[r][3], xv, w3);
                }
            }
        }
    }

    // Epilogue: add modulated bias, write coalesced float2 per lane.
    float bv[4];
#pragma unroll
    for (int o = 0; o < 4; o++) bv[o] = g_bfinal[b * COUT + obase + o];

#pragma unroll
    for (int o = 0; o < 4; o++) {
        float* ob = out + (((size_t)b * COUT + obase + o) * H_ + gy0) * W_ + gx0 + cx;
#pragma unroll
        for (int r = 0; r < 4; r++) {
            float a, bb;
            unpack2(acc[r][o], a, bb);
            float2 st = make_float2(a + bv[o], bb + bv[o]);
            *(float2*)(ob + r * W_) = st;
        }
    }
}

// ---------------------------------------------------------------------------
extern "C" void kernel_launch(void* const* d_in, const int* in_sizes, int n_in,
                              void* d_out, int out_size) {
    const float* x    = (const float*)d_in[0];
    const float* cond = (const float*)d_in[1];
    const float* lpe  = (const float*)d_in[2];
    const float* w    = (const float*)d_in[3];
    const float* bias = (const float*)d_in[4];
    const float* wa_w = (const float*)d_in[5];
    const float* wa_b = (const float*)d_in[6];
    const float* ba_w = (const float*)d_in[7];
    const float* ba_b = (const float*)d_in[8];
    float* out = (float*)d_out;

    cudaFuncSetAttribute(conv_kernel,
                         cudaFuncAttributeMaxDynamicSharedMemorySize, SMEM_BYTES);

    adapt_kernel<<<128, 256>>>(cond, lpe, wa_w, wa_b, ba_w, ba_b, bias);

    dim3 grid(W_ / 64, H_ / 4, B_);
    conv_kernel<<<grid, 256, SMEM_BYTES>>>(x, w, out);
}

// round 2
// speedup vs baseline: 1.0999x; 1.0999x over previous
#include <cuda_runtime.h>

#define B_    16
#define CIN   32
#define COUT  32
#define H_    256
#define W_    256
#define EMB2  512
#define XPITCH 72   // 66 cols padded to 72 (288B rows, 8B aligned)

typedef unsigned long long u64;

__device__ float g_wadapt[B_ * CIN];   // per-sample input-channel scale
__device__ float g_bfinal[B_ * COUT];  // bias[o] * badapt[b,o]

// ---------------------------------------------------------------------------
// f32x2 packed helpers (Blackwell packed fp32 FMA — 2x scalar FFMA rate)
// ---------------------------------------------------------------------------
__device__ __forceinline__ u64 pack2(float lo, float hi) {
    u64 r;
    asm("mov.b64 %0, {%1, %2};" : "=l"(r)
        : "r"(__float_as_uint(lo)), "r"(__float_as_uint(hi)));
    return r;
}
__device__ __forceinline__ void unpack2(u64 v, float& lo, float& hi) {
    unsigned a, b;
    asm("mov.b64 {%0, %1}, %2;" : "=r"(a), "=r"(b) : "l"(v));
    lo = __uint_as_float(a);
    hi = __uint_as_float(b);
}
__device__ __forceinline__ void fma2(u64& d, u64 a, u64 b) {
    asm("fma.rn.f32x2 %0, %1, %2, %0;" : "+l"(d) : "l"(a), "l"(b));
}

// ---------------------------------------------------------------------------
// Kernel A: adapt GEMVs (one warp per dot product; 1024 dots)
// ---------------------------------------------------------------------------
__global__ void adapt_kernel(const float* __restrict__ cond,
                             const float* __restrict__ lpe,
                             const float* __restrict__ wa_w,
                             const float* __restrict__ wa_b,
                             const float* __restrict__ ba_w,
                             const float* __restrict__ ba_b,
                             const float* __restrict__ bias) {
    int gw   = blockIdx.x * (blockDim.x >> 5) + (threadIdx.x >> 5);
    int lane = threadIdx.x & 31;
    if (gw >= 2 * B_ * CIN) return;
    int isB = (gw >= B_ * CIN);
    int idx = isB ? gw - B_ * CIN : gw;
    int b = idx >> 5, c = idx & 31;

    const float4* w4 = (const float4*)((isB ? ba_w : wa_w) + c * EMB2);
    const float4* c4 = (const float4*)(cond + b * 256);
    const float4* l4 = (const float4*)(lpe  + b * 256);

    float s = 0.f;
#pragma unroll
    for (int k = 0; k < 4; k++) {
        int j = lane + 32 * k;
        float4 iv = (j < 64) ? c4[j] : l4[j - 64];
        float4 wv = w4[j];
        s += iv.x * wv.x + iv.y * wv.y + iv.z * wv.z + iv.w * wv.w;
    }
#pragma unroll
    for (int off = 16; off; off >>= 1) s += __shfl_xor_sync(0xffffffffu, s, off);

    if (lane == 0) {
        if (isB) g_bfinal[idx] = bias[c] * (s + ba_b[c]);
        else     g_wadapt[idx] = s + wa_b[c];
    }
}

// ---------------------------------------------------------------------------
// Kernel B: shared-weight 3x3 SAME conv on wadapt-scaled weights.
// 512 threads = 16 warps, 1 CTA. Tile: 64 (w) x 4 (h), one batch, all 32 Cout.
// Warp w owns Cout {2w, 2w+1}; lane l owns columns {2l, 2l+1} x 4 rows.
// SMEM: ws = dup-packed scaled weights, layout [ci][kl][o] (LDS.128/kl) 72KB
//       xs = input tile with halo [ci][6][72] 54KB
// ---------------------------------------------------------------------------
#define WS_U64   (CIN * COUT * 9)                 // 9216
#define XS_FLT   (CIN * 6 * XPITCH)               // 13824
#define SMEM_BYTES (WS_U64 * 8 + XS_FLT * 4)      // 73728 + 55296 = 129024
#define NTHR 512

__global__ void __launch_bounds__(NTHR, 1)
conv_kernel(const float* __restrict__ x,
            const float* __restrict__ weights,
            float* __restrict__ out) {
    extern __shared__ __align__(16) char smem_raw[];
    u64*   ws = (u64*)smem_raw;
    float* xs = (float*)(smem_raw + WS_U64 * 8);
    __shared__ float wad[CIN];

    const int tid = threadIdx.x;
    const int b   = blockIdx.z;
    const int gy0 = blockIdx.y * 4;
    const int gx0 = blockIdx.x * 64;

    if (tid < CIN) wad[tid] = g_wadapt[b * CIN + tid];
    __syncthreads();

    // Fill ws: source layout [i][o][kl] -> dest [i][kl][o], scaled, dup-packed.
#pragma unroll
    for (int k = 0; k < WS_U64 / NTHR; k++) {        // 18 iters
        int e   = tid + k * NTHR;                    // 0..9215
        int i   = e / 288;
        int rem = e - i * 288;
        int o   = rem / 9;
        int kl  = rem - o * 9;
        float v = weights[e] * wad[i];
        ws[(i * 9 + kl) * 32 + o] = pack2(v, v);
    }

    // Fill xs tile with halo (zero padding at image borders).
    const float* xb = x + (size_t)b * CIN * H_ * W_;
    for (int e = tid; e < CIN * 6 * 66; e += NTHR) {
        int c = e % 66;
        int t = e / 66;
        int r = t % 6;
        int i = t / 6;
        int gy = gy0 + r - 1;
        int gx = gx0 + c - 1;
        float v = 0.f;
        if (gy >= 0 && gy < H_ && gx >= 0 && gx < W_)
            v = xb[(size_t)i * (H_ * W_) + gy * W_ + gx];
        xs[(i * 6 + r) * XPITCH + c] = v;
    }
    __syncthreads();

    const int warp  = tid >> 5;
    const int lane  = tid & 31;
    const int obase = warp * 2;       // 2 Cout per warp
    const int cx    = 2 * lane;

    u64 acc[4][2];
#pragma unroll
    for (int r = 0; r < 4; r++) { acc[r][0] = 0ULL; acc[r][1] = 0ULL; }

    for (int ci = 0; ci < CIN; ci++) {
        // x window: 6 rows x 4 cols -> 3 column-pair variants per row
        u64 xp[6][3];
        const float* xr = xs + (ci * 6) * XPITCH + cx;
#pragma unroll
        for (int r = 0; r < 6; r++) {
            u64 a0 = *(const u64*)(xr + r * XPITCH);       // (x0,x1)
            u64 a2 = *(const u64*)(xr + r * XPITCH + 2);   // (x2,x3)
            float f0, f1, f2, f3;
            unpack2(a0, f0, f1);
            unpack2(a2, f2, f3);
            xp[r][0] = a0;
            xp[r][1] = pack2(f1, f2);
            xp[r][2] = a2;
        }

        const u64* wk = ws + ci * 288 + obase;   // [kl][32] stride 32 u64
#pragma unroll
        for (int kr = 0; kr < 3; kr++) {
#pragma unroll
            for (int kc = 0; kc < 3; kc++) {
                const int kl = kr * 3 + kc;
                ulonglong2 wv = *(const ulonglong2*)(wk + kl * 32);  // LDS.128
#pragma unroll
                for (int r = 0; r < 4; r++) {
                    u64 xv = xp[r + kr][kc];
                    fma2(acc[r][0], xv, wv.x);
                    fma2(acc[r][1], xv, wv.y);
                }
            }
        }
    }

    // Epilogue: add modulated bias, coalesced float2 stores.
    float bv0 = g_bfinal[b * COUT + obase];
    float bv1 = g_bfinal[b * COUT + obase + 1];

#pragma unroll
    for (int o = 0; o < 2; o++) {
        float bv = o ? bv1 : bv0;
        float* ob = out + (((size_t)b * COUT + obase + o) * H_ + gy0) * W_ + gx0 + cx;
#pragma unroll
        for (int r = 0; r < 4; r++) {
            float a, bb;
            unpack2(acc[r][o], a, bb);
            float2 st = make_float2(a + bv, bb + bv);
            *(float2*)(ob + r * W_) = st;
        }
    }
}

// ---------------------------------------------------------------------------
extern "C" void kernel_launch(void* const* d_in, const int* in_sizes, int n_in,
                              void* d_out, int out_size) {
    const float* x    = (const float*)d_in[0];
    const float* cond = (const float*)d_in[1];
    const float* lpe  = (const float*)d_in[2];
    const float* w    = (const float*)d_in[3];
    const float* bias = (const float*)d_in[4];
    const float* wa_w = (const float*)d_in[5];
    const float* wa_b = (const float*)d_in[6];
    const float* ba_w = (const float*)d_in[7];
    const float* ba_b = (const float*)d_in[8];
    float* out = (float*)d_out;

    cudaFuncSetAttribute(conv_kernel,
                         cudaFuncAttributeMaxDynamicSharedMemorySize, SMEM_BYTES);

    adapt_kernel<<<128, 256>>>(cond, lpe, wa_w, wa_b, ba_w, ba_b, bias);

    dim3 grid(W_ / 64, H_ / 4, B_);
    conv_kernel<<<grid, NTHR, SMEM_BYTES>>>(x, w, out);
}

// round 3
// speedup vs baseline: 1.1961x; 1.0875x over previous
#include <cuda_runtime.h>

#define B_    16
#define CIN   32
#define COUT  32
#define H_    256
#define W_    256
#define EMB2  512
#define XPITCH 72   // 66 used cols padded to 72 floats (288B rows)

typedef unsigned long long u64;

__device__ float g_wadapt[B_ * CIN];   // per-sample input-channel scale
__device__ float g_bfinal[B_ * COUT];  // bias[o] * badapt[b,o]

// ---------------------------------------------------------------------------
// f32x2 packed helpers
// ---------------------------------------------------------------------------
__device__ __forceinline__ u64 pack2(float lo, float hi) {
    u64 r;
    asm("mov.b64 %0, {%1, %2};" : "=l"(r)
        : "r"(__float_as_uint(lo)), "r"(__float_as_uint(hi)));
    return r;
}
__device__ __forceinline__ void unpack2(u64 v, float& lo, float& hi) {
    unsigned a, b;
    asm("mov.b64 {%0, %1}, %2;" : "=r"(a), "=r"(b) : "l"(v));
    lo = __uint_as_float(a);
    hi = __uint_as_float(b);
}
__device__ __forceinline__ void fma2(u64& d, u64 a, u64 b) {
    asm("fma.rn.f32x2 %0, %1, %2, %0;" : "+l"(d) : "l"(a), "l"(b));
}

// ---------------------------------------------------------------------------
// Kernel A: adapt GEMVs (one warp per dot; 1024 dots)
// ---------------------------------------------------------------------------
__global__ void adapt_kernel(const float* __restrict__ cond,
                             const float* __restrict__ lpe,
                             const float* __restrict__ wa_w,
                             const float* __restrict__ wa_b,
                             const float* __restrict__ ba_w,
                             const float* __restrict__ ba_b,
                             const float* __restrict__ bias) {
    int gw   = blockIdx.x * (blockDim.x >> 5) + (threadIdx.x >> 5);
    int lane = threadIdx.x & 31;
    if (gw >= 2 * B_ * CIN) return;
    int isB = (gw >= B_ * CIN);
    int idx = isB ? gw - B_ * CIN : gw;
    int b = idx >> 5, c = idx & 31;

    const float4* w4 = (const float4*)((isB ? ba_w : wa_w) + c * EMB2);
    const float4* c4 = (const float4*)(cond + b * 256);
    const float4* l4 = (const float4*)(lpe  + b * 256);

    float s = 0.f;
#pragma unroll
    for (int k = 0; k < 4; k++) {
        int j = lane + 32 * k;
        float4 iv = (j < 64) ? c4[j] : l4[j - 64];
        float4 wv = w4[j];
        s += iv.x * wv.x + iv.y * wv.y + iv.z * wv.z + iv.w * wv.w;
    }
#pragma unroll
    for (int off = 16; off; off >>= 1) s += __shfl_xor_sync(0xffffffffu, s, off);

    if (lane == 0) {
        if (isB) g_bfinal[idx] = bias[c] * (s + ba_b[c]);
        else     g_wadapt[idx] = s + wa_b[c];
    }
}

// ---------------------------------------------------------------------------
// Kernel B: 512 thr = 16 warps, 1 CTA/SM. Tile 64(w) x 8(h), one batch, all
// 32 Cout. warp = (row-group rg = warp>>3, Cout-group og = (warp&7)*4).
// Lane owns column pair {2l,2l+1} x 4 rows x 4 Cout = 16 f32x2 accumulators.
// SMEM: ws dup-packed scaled weights [ci][kl][o] (2x LDS.128 per kl) 72KB
//       xs input tile with halo [ci][10][72] 90KB
// ---------------------------------------------------------------------------
#define WS_U64   (CIN * COUT * 9)                     // 9216
#define XS_FLT   (CIN * 10 * XPITCH)                  // 23040
#define SMEM_BYTES (WS_U64 * 8 + XS_FLT * 4)          // 73728 + 92160 = 165888
#define NTHR 512

// One ci step: consume raw window `a` (for channel ci), prefetch channel
// cin's raw window into `an`. acc[r][o] accumulates 4 rows x 4 Cout.
__device__ __forceinline__ void ci_step(
    const u64* __restrict__ ws, const float* __restrict__ xwarp,
    int ci, int cin, int og,
    u64 (&a)[6][2], u64 (&an)[6][2], u64 (&acc)[4][4]) {

    // Prefetch next channel's raw x window (12 LDS.64, independent).
    const float* xr = xwarp + cin * (10 * XPITCH);
#pragma unroll
    for (int r = 0; r < 6; r++) {
        an[r][0] = *(const u64*)(xr + r * XPITCH);
        an[r][1] = *(const u64*)(xr + r * XPITCH + 2);
    }

    // Build middle column-pair variants (6 packs).
    u64 xm[6];
#pragma unroll
    for (int r = 0; r < 6; r++) {
        float f0, f1, f2, f3;
        unpack2(a[r][0], f0, f1);
        unpack2(a[r][1], f2, f3);
        xm[r] = pack2(f1, f2);
    }

    const u64* wk = ws + ci * 288 + og;   // [kl][32] stride 32 u64
#pragma unroll
    for (int kr = 0; kr < 3; kr++) {
#pragma unroll
        for (int kc = 0; kc < 3; kc++) {
            const int kl = kr * 3 + kc;
            const ulonglong2* wp = (const ulonglong2*)(wk + kl * 32);
            ulonglong2 wA = wp[0];   // (o0,o0),(o1,o1)
            ulonglong2 wB = wp[1];   // (o2,o2),(o3,o3)
#pragma unroll
            for (int r = 0; r < 4; r++) {
                u64 xv = (kc == 0) ? a[r + kr][0]
                       : (kc == 2) ? a[r + kr][1]
                                   : xm[r + kr];
                fma2(acc[r][0], xv, wA.x);
                fma2(acc[r][1], xv, wA.y);
                fma2(acc[r][2], xv, wB.x);
                fma2(acc[r][3], xv, wB.y);
            }
        }
    }
}

__global__ void __launch_bounds__(NTHR, 1)
conv_kernel(const float* __restrict__ x,
            const float* __restrict__ weights,
            float* __restrict__ out) {
    extern __shared__ __align__(16) char smem_raw[];
    u64*   ws = (u64*)smem_raw;
    float* xs = (float*)(smem_raw + WS_U64 * 8);
    __shared__ float wad[CIN];

    const int tid = threadIdx.x;
    const int b   = blockIdx.z;
    const int gy0 = blockIdx.y * 8;
    const int gx0 = blockIdx.x * 64;

    if (tid < CIN) wad[tid] = g_wadapt[b * CIN + tid];
    __syncthreads();

    // Fill ws: source [i][o][kl] -> dest [i][kl][o], scaled, dup-packed.
#pragma unroll
    for (int k = 0; k < WS_U64 / NTHR; k++) {        // 18 iters
        int e   = tid + k * NTHR;
        int i   = e / 288;
        int rem = e - i * 288;
        int o   = rem / 9;
        int kl  = rem - o * 9;
        float v = weights[e] * wad[i];
        ws[(i * 9 + kl) * 32 + o] = pack2(v, v);
    }

    // Fill xs tile with halo (zero-padded at image borders).
    const float* xb = x + (size_t)b * CIN * H_ * W_;
    for (int e = tid; e < CIN * 10 * 66; e += NTHR) {
        int c = e % 66;
        int t = e / 66;
        int r = t % 10;
        int i = t / 10;
        int gy = gy0 + r - 1;
        int gx = gx0 + c - 1;
        float v = 0.f;
        if (gy >= 0 && gy < H_ && gx >= 0 && gx < W_)
            v = xb[(size_t)i * (H_ * W_) + gy * W_ + gx];
        xs[(i * 10 + r) * XPITCH + c] = v;
    }
    __syncthreads();

    const int warp = tid >> 5;
    const int lane = tid & 31;
    const int rg   = warp >> 3;          // row group 0/1
    const int og   = (warp & 7) * 4;     // 4 Cout per warp
    const int cx   = 2 * lane;

    const float* xwarp = xs + (rg * 4) * XPITCH + cx;

    u64 acc[4][4];
#pragma unroll
    for (int r = 0; r < 4; r++)
#pragma unroll
        for (int o = 0; o < 4; o++) acc[r][o] = 0ULL;

    // Load ci=0 raw window, then ping-pong through channels.
    u64 a[6][2], bbuf[6][2];
#pragma unroll
    for (int r = 0; r < 6; r++) {
        a[r][0] = *(const u64*)(xwarp + r * XPITCH);
        a[r][1] = *(const u64*)(xwarp + r * XPITCH + 2);
    }

    for (int ci = 0; ci < CIN; ci += 2) {
        int c1 = ci + 1;
        int c2 = (ci + 2 < CIN) ? ci + 2 : CIN - 1;   // clamped prefetch
        ci_step(ws, xwarp, ci, c1, og, a, bbuf, acc);
        ci_step(ws, xwarp, c1, c2, og, bbuf, a, acc);
    }

    // Epilogue: modulated bias add, coalesced float2 stores.
    const int gy = gy0 + rg * 4;
#pragma unroll
    for (int o = 0; o < 4; o++) {
        float bv = g_bfinal[b * COUT + og + o];
        float* ob = out + (((size_t)b * COUT + og + o) * H_ + gy) * W_ + gx0 + cx;
#pragma unroll
        for (int r = 0; r < 4; r++) {
            float lo, hi;
            unpack2(acc[r][o], lo, hi);
            *(float2*)(ob + r * W_) = make_float2(lo + bv, hi + bv);
        }
    }
}

// ---------------------------------------------------------------------------
extern "C" void kernel_launch(void* const* d_in, const int* in_sizes, int n_in,
                              void* d_out, int out_size) {
    const float* x    = (const float*)d_in[0];
    const float* cond = (const float*)d_in[1];
    const float* lpe  = (const float*)d_in[2];
    const float* w    = (const float*)d_in[3];
    const float* bias = (const float*)d_in[4];
    const float* wa_w = (const float*)d_in[5];
    const float* wa_b = (const float*)d_in[6];
    const float* ba_w = (const float*)d_in[7];
    const float* ba_b = (const float*)d_in[8];
    float* out = (float*)d_out;

    cudaFuncSetAttribute(conv_kernel,
                         cudaFuncAttributeMaxDynamicSharedMemorySize, SMEM_BYTES);

    adapt_kernel<<<128, 256>>>(cond, lpe, wa_w, wa_b, ba_w, ba_b, bias);

    dim3 grid(W_ / 64, H_ / 8, B_);
    conv_kernel<<<grid, NTHR, SMEM_BYTES>>>(x, w, out);
}

// round 5
// speedup vs baseline: 1.7548x; 1.4671x over previous
#include <cuda_runtime.h>
#include <cuda_bf16.h>
#include <cstdint>

#define B_    16
#define CIN   32
#define COUT  32
#define H_    256
#define W_    256
#define EMB2  512

__device__ float g_wadapt[B_ * CIN];
__device__ float g_bfinal[B_ * COUT];

// ---------------------------------------------------------------------------
// Kernel A: adapt GEMVs (one warp per dot; 1024 dots)
// ---------------------------------------------------------------------------
__global__ void adapt_kernel(const float* __restrict__ cond,
                             const float* __restrict__ lpe,
                             const float* __restrict__ wa_w,
                             const float* __restrict__ wa_b,
                             const float* __restrict__ ba_w,
                             const float* __restrict__ ba_b,
                             const float* __restrict__ bias) {
    int gw   = blockIdx.x * (blockDim.x >> 5) + (threadIdx.x >> 5);
    int lane = threadIdx.x & 31;
    if (gw >= 2 * B_ * CIN) return;
    int isB = (gw >= B_ * CIN);
    int idx = isB ? gw - B_ * CIN : gw;
    int b = idx >> 5, c = idx & 31;

    const float4* w4 = (const float4*)((isB ? ba_w : wa_w) + c * EMB2);
    const float4* c4 = (const float4*)(cond + b * 256);
    const float4* l4 = (const float4*)(lpe  + b * 256);

    float s = 0.f;
#pragma unroll
    for (int k = 0; k < 4; k++) {
        int j = lane + 32 * k;
        float4 iv = (j < 64) ? c4[j] : l4[j - 64];
        float4 wv = w4[j];
        s += iv.x * wv.x + iv.y * wv.y + iv.z * wv.z + iv.w * wv.w;
    }
#pragma unroll
    for (int off = 16; off; off >>= 1) s += __shfl_xor_sync(0xffffffffu, s, off);

    if (lane == 0) {
        if (isB) g_bfinal[idx] = bias[c] * (s + ba_b[c]);
        else     g_wadapt[idx] = s + wa_b[c];
    }
}

// ---------------------------------------------------------------------------
// ldmatrix / mma.sync helpers (generic PTX, sm_80+ — compiles for compute_103)
// ---------------------------------------------------------------------------
__device__ __forceinline__ uint32_t smem_u32(const void* p) {
    uint32_t a;
    asm("{ .reg .u64 t; cvta.to.shared.u64 t, %1; cvt.u32.u64 %0, t; }"
        : "=r"(a) : "l"(p));
    return a;
}
__device__ __forceinline__ void ldsm4(uint32_t* r, uint32_t a) {
    asm volatile("ldmatrix.sync.aligned.m8n8.x4.shared.b16 {%0,%1,%2,%3}, [%4];"
                 : "=r"(r[0]), "=r"(r[1]), "=r"(r[2]), "=r"(r[3]) : "r"(a));
}
__device__ __forceinline__ void ldsm2(uint32_t* r, uint32_t a) {
    asm volatile("ldmatrix.sync.aligned.m8n8.x2.shared.b16 {%0,%1}, [%2];"
                 : "=r"(r[0]), "=r"(r[1]) : "r"(a));
}
__device__ __forceinline__ void mma16816(float* d, const uint32_t* a,
                                         const uint32_t* b) {
    asm volatile(
        "mma.sync.aligned.m16n8k16.row.col.f32.bf16.bf16.f32 "
        "{%0,%1,%2,%3}, {%4,%5,%6,%7}, {%8,%9}, {%0,%1,%2,%3};"
        : "+f"(d[0]), "+f"(d[1]), "+f"(d[2]), "+f"(d[3])
        : "r"(a[0]), "r"(a[1]), "r"(a[2]), "r"(a[3]), "r"(b[0]), "r"(b[1]));
}

// ---------------------------------------------------------------------------
// Kernel B: implicit-GEMM conv on mma.sync (bf16 hi/lo split, fp32 accum).
// CTA: batch b, 2 output rows x 128 cols, all 32 Cout. 512 thr = 16 warps,
// warp w owns output pixels [16w, 16w+16).
// A smem: 520 pixel-rows (4 halo rows x 130 halo cols) x 128B:
//   [32x bf16 hi | 32x bf16 lo], 16B chunks XOR-swizzled by (p&7).
// B smem: 288 rows (tap*32+o) x 128B, same format, swizzled by (r&7).
// Tap (dr,dc) = A pixel-row shift dr*130+dc. 3 MMA products: hh, lh, hl.
// ---------------------------------------------------------------------------
#define APIX   520
#define ABYTES (APIX * 128)             // 66560
#define BROWS  288
#define BBYTES (BROWS * 128)            // 36864
#define SMEM_TOTAL (ABYTES + BBYTES)    // 103424
#define NTHR 512

__global__ void __launch_bounds__(NTHR, 1)
conv_mma(const float* __restrict__ x,
         const float* __restrict__ weights,
         float* __restrict__ out) {
    extern __shared__ __align__(128) char smem[];
    char* smA = smem;
    char* smB = smem + ABYTES;
    __shared__ float wadc[CIN];
    __shared__ float bfc[COUT];

    const int tid  = threadIdx.x;
    const int warp = tid >> 5;
    const int lane = tid & 31;
    const int b    = blockIdx.z;
    const int gy0  = blockIdx.y * 2;
    const int gx0  = blockIdx.x * 128;

    if (tid < CIN)  wadc[tid] = g_wadapt[b * CIN + tid];
    if (tid < COUT) bfc[tid]  = g_bfinal[b * COUT + tid];
    __syncthreads();

    // ---- Stage B: scaled weights, hi/lo bf16 split, swizzled ----
    for (int e = tid; e < CIN * COUT * 9; e += NTHR) {
        int ci  = e / 288;
        int rem = e - ci * 288;
        int o   = rem / 9;
        int kl  = rem - o * 9;
        float v = weights[e] * wadc[ci];
        __nv_bfloat16 h = __float2bfloat16(v);
        __nv_bfloat16 l = __float2bfloat16(v - __bfloat162float(h));
        int r  = kl * 32 + o;
        int ch = (ci >> 3) ^ (r & 7);        // hi chunk
        int cl = (4 + (ci >> 3)) ^ (r & 7);  // lo chunk
        int wb = (ci & 7) * 2;
        *(__nv_bfloat16*)(smB + r * 128 + ch * 16 + wb) = h;
        *(__nv_bfloat16*)(smB + r * 128 + cl * 16 + wb) = l;
    }

    // ---- Stage A: x tile with halo, hi/lo bf16 split, swizzled ----
    const float* xb = x + (size_t)b * CIN * H_ * W_;
    for (int e = tid; e < CIN * APIX; e += NTHR) {
        int ci = e / APIX;
        int p  = e - ci * APIX;      // consecutive lanes -> consecutive cols
        int iy = p / 130;
        int ix = p - iy * 130;
        int gy = gy0 - 1 + iy;
        int gx = gx0 - 1 + ix;
        float v = 0.f;
        if ((unsigned)gy < (unsigned)H_ && (unsigned)gx < (unsigned)W_)
            v = xb[(size_t)ci * (H_ * W_) + gy * W_ + gx];
        __nv_bfloat16 h = __float2bfloat16(v);
        __nv_bfloat16 l = __float2bfloat16(v - __bfloat162float(h));
        int ch = (ci >> 3) ^ (p & 7);
        int cl = (4 + (ci >> 3)) ^ (p & 7);
        int wb = (ci & 7) * 2;
        *(__nv_bfloat16*)(smA + p * 128 + ch * 16 + wb) = h;
        *(__nv_bfloat16*)(smA + p * 128 + cl * 16 + wb) = l;
    }
    __syncthreads();

    // ---- MMA mainloop ----
    const uint32_t sbA = smem_u32(smA);
    const uint32_t sbB = smem_u32(smB);

    const int m  = warp * 16 + (lane & 15);      // output pixel of this lane's A rows
    const int p0 = (m >> 7) * 130 + (m & 127);   // tap(0,0) A pixel-row
    const int kh  = lane >> 4;                   // A: k-half select
    const int khb = (lane >> 3) & 1;             // B: k-half select (lanes 0..15)
    const int bro = lane & 7;                    // B: row within 8

    float acc[4][4];
#pragma unroll
    for (int nt = 0; nt < 4; nt++)
#pragma unroll
        for (int j = 0; j < 4; j++) acc[nt][j] = 0.f;

#pragma unroll
    for (int tap = 0; tap < 9; tap++) {
        const int pa = p0 + (tap / 3) * 130 + (tap % 3);
        const uint32_t arow = sbA + pa * 128;
        const int     psw  = pa & 7;
#pragma unroll
        for (int ks = 0; ks < 2; ks++) {
            uint32_t ah[4], al[4];
            // A hi: chunks {0,1} + kh ; A lo: chunks {4,5} + kh
            ldsm4(ah, arow + (((ks * 2 + kh)     ^ psw) << 4));
            ldsm4(al, arow + (((4 + ks * 2 + kh) ^ psw) << 4));
#pragma unroll
            for (int nt = 0; nt < 4; nt++) {
                const int r = tap * 32 + nt * 8 + bro;
                const uint32_t brow = sbB + r * 128;
                const int     rsw  = r & 7;
                uint32_t bh[2], bl[2];
                ldsm2(bh, brow + (((ks * 2 + khb)     ^ rsw) << 4));
                mma16816(acc[nt], ah, bh);   // hi * hi
                mma16816(acc[nt], al, bh);   // lo * hi
                ldsm2(bl, brow + (((4 + ks * 2 + khb) ^ rsw) << 4));
                mma16816(acc[nt], ah, bl);   // hi * lo
            }
        }
    }

    // ---- Epilogue: bias add + global stores ----
    // D frag lane map (m16n8): rows lane>>2 and (lane>>2)+8; cols (lane&3)*2+{0,1}
    const int row0 = warp * 16 + (lane >> 2);
#pragma unroll
    for (int nt = 0; nt < 4; nt++) {
#pragma unroll
        for (int j = 0; j < 4; j++) {
            int o  = nt * 8 + (lane & 3) * 2 + (j & 1);
            int mm = row0 + (j >> 1) * 8;
            int gy = gy0 + (mm >> 7);
            int gx = gx0 + (mm & 127);
            out[(((size_t)b * COUT + o) * H_ + gy) * W_ + gx] = acc[nt][j] + bfc[o];
        }
    }
}

// ---------------------------------------------------------------------------
extern "C" void kernel_launch(void* const* d_in, const int* in_sizes, int n_in,
                              void* d_out, int out_size) {
    const float* x    = (const float*)d_in[0];
    const float* cond = (const float*)d_in[1];
    const float* lpe  = (const float*)d_in[2];
    const float* w    = (const float*)d_in[3];
    const float* bias = (const float*)d_in[4];
    const float* wa_w = (const float*)d_in[5];
    const float* wa_b = (const float*)d_in[6];
    const float* ba_w = (const float*)d_in[7];
    const float* ba_b = (const float*)d_in[8];
    float* out = (float*)d_out;

    cudaFuncSetAttribute(conv_mma,
                         cudaFuncAttributeMaxDynamicSharedMemorySize, SMEM_TOTAL);

    adapt_kernel<<<128, 256>>>(cond, lpe, wa_w, wa_b, ba_w, ba_b, bias);

    dim3 grid(W_ / 128, H_ / 2, B_);
    conv_mma<<<grid, NTHR, SMEM_TOTAL>>>(x, w, out);
}

// round 6
// speedup vs baseline: 2.7892x; 1.5894x over previous
#include <cuda_runtime.h>
#include <cuda_bf16.h>
#include <cstdint>

#define B_    16
#define CIN   32
#define COUT  32
#define H_    256
#define W_    256
#define EMB2  512

__device__ float g_wadapt[B_ * CIN];
__device__ float g_bfinal[B_ * COUT];
// Pre-built B fragments: [b][set(144)][lane(32)] as (reg0,reg1).
// set = ((tap*2+ks)*2 + hl)*4 + nt
__device__ uint2 g_bfrag[B_ * 144 * 32];

// ---------------------------------------------------------------------------
// PTX helpers (generic, sm_80+)
// ---------------------------------------------------------------------------
__device__ __forceinline__ uint32_t smem_u32(const void* p) {
    uint32_t a;
    asm("{ .reg .u64 t; cvta.to.shared.u64 t, %1; cvt.u32.u64 %0, t; }"
        : "=r"(a) : "l"(p));
    return a;
}
__device__ __forceinline__ void ldsm4(uint32_t* r, uint32_t a) {
    asm volatile("ldmatrix.sync.aligned.m8n8.x4.shared.b16 {%0,%1,%2,%3}, [%4];"
                 : "=r"(r[0]), "=r"(r[1]), "=r"(r[2]), "=r"(r[3]) : "r"(a));
}
__device__ __forceinline__ void ldsm2(uint32_t* r, uint32_t a) {
    asm volatile("ldmatrix.sync.aligned.m8n8.x2.shared.b16 {%0,%1}, [%2];"
                 : "=r"(r[0]), "=r"(r[1]) : "r"(a));
}
__device__ __forceinline__ void mma16816(float* d, const uint32_t* a,
                                         uint32_t b0, uint32_t b1) {
    asm volatile(
        "mma.sync.aligned.m16n8k16.row.col.f32.bf16.bf16.f32 "
        "{%0,%1,%2,%3}, {%4,%5,%6,%7}, {%8,%9}, {%0,%1,%2,%3};"
        : "+f"(d[0]), "+f"(d[1]), "+f"(d[2]), "+f"(d[3])
        : "r"(a[0]), "r"(a[1]), "r"(a[2]), "r"(a[3]), "r"(b0), "r"(b1));
}

// ---------------------------------------------------------------------------
// Kernel A: adapt GEMVs (one warp per dot; 1024 dots)
// ---------------------------------------------------------------------------
__global__ void adapt_kernel(const float* __restrict__ cond,
                             const float* __restrict__ lpe,
                             const float* __restrict__ wa_w,
                             const float* __restrict__ wa_b,
                             const float* __restrict__ ba_w,
                             const float* __restrict__ ba_b,
                             const float* __restrict__ bias) {
    int gw   = blockIdx.x * (blockDim.x >> 5) + (threadIdx.x >> 5);
    int lane = threadIdx.x & 31;
    if (gw >= 2 * B_ * CIN) return;
    int isB = (gw >= B_ * CIN);
    int idx = isB ? gw - B_ * CIN : gw;
    int b = idx >> 5, c = idx & 31;

    const float4* w4 = (const float4*)((isB ? ba_w : wa_w) + c * EMB2);
    const float4* c4 = (const float4*)(cond + b * 256);
    const float4* l4 = (const float4*)(lpe  + b * 256);

    float s = 0.f;
#pragma unroll
    for (int k = 0; k < 4; k++) {
        int j = lane + 32 * k;
        float4 iv = (j < 64) ? c4[j] : l4[j - 64];
        float4 wv = w4[j];
        s += iv.x * wv.x + iv.y * wv.y + iv.z * wv.z + iv.w * wv.w;
    }
#pragma unroll
    for (int off = 16; off; off >>= 1) s += __shfl_xor_sync(0xffffffffu, s, off);

    if (lane == 0) {
        if (isB) g_bfinal[idx] = bias[c] * (s + ba_b[c]);
        else     g_wadapt[idx] = s + wa_b[c];
    }
}

// ---------------------------------------------------------------------------
// Kernel A2: per-batch B-fragment prep. One CTA per batch (512 thr).
// Builds scaled hi/lo-split swizzled B in smem (exact R5 layout), then
// emulates the mainloop's ldsm2 and stores per-lane fragments to g_bfrag.
// ---------------------------------------------------------------------------
#define BROWS  288
#define BBYTES (BROWS * 128)

__global__ void __launch_bounds__(512)
bfrag_prep(const float* __restrict__ weights) {
    __shared__ char smB[BBYTES];
    const int tid  = threadIdx.x;
    const int warp = tid >> 5;
    const int lane = tid & 31;
    const int b    = blockIdx.x;

    for (int e = tid; e < CIN * COUT * 9; e += 512) {
        int ci  = e / 288;
        int rem = e - ci * 288;
        int o   = rem / 9;
        int kl  = rem - o * 9;
        float v = weights[e] * g_wadapt[b * CIN + ci];
        __nv_bfloat16 h = __float2bfloat16(v);
        __nv_bfloat16 l = __float2bfloat16(v - __bfloat162float(h));
        int r  = kl * 32 + o;
        int ch = (ci >> 3) ^ (r & 7);
        int cl = (4 + (ci >> 3)) ^ (r & 7);
        int wb = (ci & 7) * 2;
        *(__nv_bfloat16*)(smB + r * 128 + ch * 16 + wb) = h;
        *(__nv_bfloat16*)(smB + r * 128 + cl * 16 + wb) = l;
    }
    __syncthreads();

    const uint32_t sbB = smem_u32(smB);
    for (int s = warp; s < 144; s += 16) {
        int tap = s >> 4, ks = (s >> 3) & 1, hl = (s >> 2) & 1, nt = s & 3;
        int r  = tap * 32 + nt * 8 + (lane & 7);
        int c0 = hl * 4 + ks * 2 + ((lane >> 3) & 1);
        uint32_t f[2];
        ldsm2(f, sbB + r * 128 + (uint32_t)((c0 ^ (r & 7)) << 4));
        g_bfrag[((size_t)b * 144 + s) * 32 + lane] = make_uint2(f[0], f[1]);
    }
}

// ---------------------------------------------------------------------------
// Kernel B: conv mainloop. CTA = batch b, 2 output rows x 64 cols, all 32
// Cout; 256 thr = 8 warps; warp owns 16 output pixels. 3 CTAs/SM.
// A smem: 264 pixel-rows (4 halo rows x 66 halo cols) x 128B
//   [32x bf16 hi | 32x bf16 lo], 16B chunks XOR-swizzled by (p&7).
// B: fragments straight from g_bfrag via LDG.64 (L2-resident).
// ---------------------------------------------------------------------------
#define APIX   264
#define ABYTES (APIX * 128)     // 33792
#define NTHR 256

__global__ void __launch_bounds__(NTHR, 3)
conv_mma(const float* __restrict__ x,
         float* __restrict__ out) {
    extern __shared__ __align__(128) char smA[];
    __shared__ float bfc[COUT];

    const int tid  = threadIdx.x;
    const int warp = tid >> 5;
    const int lane = tid & 31;
    const int b    = blockIdx.z;
    const int gy0  = blockIdx.y * 2;
    const int gx0  = blockIdx.x * 64;

    if (tid < COUT) bfc[tid] = g_bfinal[b * COUT + tid];

    // ---- Stage A: x tile with halo, hi/lo bf16 split, swizzled ----
    const float* xb = x + (size_t)b * CIN * H_ * W_;
    for (int e = tid; e < CIN * APIX; e += NTHR) {
        int ci = e / APIX;
        int p  = e - ci * APIX;
        int iy = p / 66;
        int ix = p - iy * 66;
        int gy = gy0 - 1 + iy;
        int gx = gx0 - 1 + ix;
        float v = 0.f;
        if ((unsigned)gy < (unsigned)H_ && (unsigned)gx < (unsigned)W_)
            v = xb[(size_t)ci * (H_ * W_) + gy * W_ + gx];
        __nv_bfloat16 h = __float2bfloat16(v);
        __nv_bfloat16 l = __float2bfloat16(v - __bfloat162float(h));
        int ch = (ci >> 3) ^ (p & 7);
        int cl = (4 + (ci >> 3)) ^ (p & 7);
        int wb = (ci & 7) * 2;
        *(__nv_bfloat16*)(smA + p * 128 + ch * 16 + wb) = h;
        *(__nv_bfloat16*)(smA + p * 128 + cl * 16 + wb) = l;
    }
    __syncthreads();

    // ---- MMA mainloop ----
    const uint32_t sbA = smem_u32(smA);
    const int m  = warp * 16 + (lane & 15);
    const int p0 = (m >> 6) * 66 + (m & 63);   // tap(0,0) A pixel-row
    const int kh = lane >> 4;
    const uint2* __restrict__ bfb = g_bfrag + (size_t)b * 144 * 32 + lane;

    float acc[4][4];
#pragma unroll
    for (int nt = 0; nt < 4; nt++)
#pragma unroll
        for (int j = 0; j < 4; j++) acc[nt][j] = 0.f;

#pragma unroll
    for (int tap = 0; tap < 9; tap++) {
        const int pa = p0 + (tap / 3) * 66 + (tap % 3);
        const uint32_t arow = sbA + pa * 128;
        const int     psw  = pa & 7;
#pragma unroll
        for (int ks = 0; ks < 2; ks++) {
            // B fragments for this (tap, ks): hl*4+nt, 8 LDG.64 (L2 hits)
            uint2 bf[8];
            const int s0 = (tap * 2 + ks) * 8;
#pragma unroll
            for (int i = 0; i < 8; i++) bf[i] = bfb[(s0 + i) * 32];

            uint32_t ah[4], al[4];
            ldsm4(ah, arow + (uint32_t)((((ks * 2 + kh)     ^ psw) << 4)));
            ldsm4(al, arow + (uint32_t)(((4 + ks * 2 + kh) ^ psw) << 4));
#pragma unroll
            for (int nt = 0; nt < 4; nt++) {
                mma16816(acc[nt], ah, bf[nt].x,     bf[nt].y);      // hi*hi
                mma16816(acc[nt], al, bf[nt].x,     bf[nt].y);      // lo*hi
                mma16816(acc[nt], ah, bf[4 + nt].x, bf[4 + nt].y);  // hi*lo
            }
        }
    }

    // ---- Epilogue: bias add + stores ----
    const int row0 = warp * 16 + (lane >> 2);
#pragma unroll
    for (int nt = 0; nt < 4; nt++) {
#pragma unroll
        for (int j = 0; j < 4; j++) {
            int o  = nt * 8 + (lane & 3) * 2 + (j & 1);
            int mm = row0 + (j >> 1) * 8;
            int gy = gy0 + (mm >> 6);
            int gx = gx0 + (mm & 63);
            out[(((size_t)b * COUT + o) * H_ + gy) * W_ + gx] = acc[nt][j] + bfc[o];
        }
    }
}

// ---------------------------------------------------------------------------
extern "C" void kernel_launch(void* const* d_in, const int* in_sizes, int n_in,
                              void* d_out, int out_size) {
    const float* x    = (const float*)d_in[0];
    const float* cond = (const float*)d_in[1];
    const float* lpe  = (const float*)d_in[2];
    const float* w    = (const float*)d_in[3];
    const float* bias = (const float*)d_in[4];
    const float* wa_w = (const float*)d_in[5];
    const float* wa_b = (const float*)d_in[6];
    const float* ba_w = (const float*)d_in[7];
    const float* ba_b = (const float*)d_in[8];
    float* out = (float*)d_out;

    adapt_kernel<<<128, 256>>>(cond, lpe, wa_w, wa_b, ba_w, ba_b, bias);
    bfrag_prep<<<B_, 512>>>(w);

    dim3 grid(W_ / 64, H_ / 2, B_);
    conv_mma<<<grid, NTHR, ABYTES>>>(x, out);
}